// round 8
// baseline (speedup 1.0000x reference)
#include <cuda_runtime.h>

// Photonic mesh simulator, N=128. R8: 4 warps per column (1 pair per thread)
// to use all 4 SMSPs (R7 was single-warp issue-bound at 93% of the 1-SMSP
// ceiling), combined with R7's copy-free ring prefetch (depth 8 now, since
// per-layer issue time dropped 4x and load->use must still cover L2 latency).
// Cross exchange: shfl inside warps; 3 warp-boundary values via a tiny
// double-buffered smem patch + one __syncthreads per cross.

#define N_ 128
#define NLAYERS 255   // 2N-1
#define RING 8

// (cos,sin) per (layer, mode); + RING+1 padded layers so prefetch never OOBs
__device__ __align__(16) float2 g_cs[(NLAYERS + RING + 1) * N_];

__global__ void precompute_cs_kernel(const float* __restrict__ theta_even) {
    int idx = blockIdx.x * blockDim.x + threadIdx.x;
    if (idx < NLAYERS * N_) {
        float s, c;
        sincosf(theta_even[idx], &s, &c);
        g_cs[idx] = make_float2(c, s);
    } else if (idx < (NLAYERS + RING + 1) * N_) {
        g_cs[idx] = make_float2(1.0f, 0.0f);  // padding (never used in math)
    }
}

__global__ void __launch_bounds__(N_, 1) mesh_kernel(
    const float* __restrict__ theta_in,
    const float* __restrict__ theta_out,
    float* __restrict__ out)
{
    // B_mmi = aM*[[p, iq],[iq, p]], aM=sqrt(0.95), p=sqrt(0.505), q=sqrt(0.495)
    constexpr float PM = 0.6926399f;
    constexpr float QM = 0.6857478f;
    // B_x = aX*[[s, it],[it, s]], aX=sqrt(0.98), s=sqrt(0.01), t=sqrt(0.99)
    constexpr float PX = 0.09899495f;
    constexpr float QX = 0.9849873f;
    constexpr float CE = 0.9849873f;   // endpoint scalar aX*sqrt(1-CT)

    const int tid  = threadIdx.x;      // pair index m: rows (2m, 2m+1)
    const int lane = tid & 31;
    const int w    = tid >> 5;         // warp id 0..3
    const int col  = blockIdx.x;       // column

    // double-buffered warp-boundary patch: a of lane0, b of lane31, per warp
    __shared__ float2 sm_a[2][4];
    __shared__ float2 sm_b[2][4];

    // state: (a,b) = complex rows (2*tid, 2*tid+1)
    float2 a = make_float2(0.f, 0.f);
    float2 b = make_float2(0.f, 0.f);
    if (tid == col) {
        float si, ci;
        sincosf(theta_in[col], &si, &ci);
        a = make_float2(PM * ci, PM * si);     // aM*p * e^{i th}
        b = make_float2(-QM * si, QM * ci);    // aM*q * i * e^{i th}
    }

    // phase ring: this thread needs (cos,sin) of mode tid each layer
    const float2* cs = g_cs + tid;
    float2 q[RING];
    #pragma unroll
    for (int j = 0; j < RING; ++j) q[j] = cs[j * N_];

    // phase (even row) + MMI_EVEN on the owned pair
    auto layer = [&](float2 f) {
        float ar = fmaf(a.x, f.x, -a.y * f.y);
        float ai = fmaf(a.x, f.y,  a.y * f.x);
        float n0r = fmaf(PM, ar,  -QM * b.y);
        float n0i = fmaf(PM, ai,   QM * b.x);
        float n1r = fmaf(PM, b.x, -QM * ai);
        float n1i = fmaf(PM, b.y,  QM * ar);
        a = make_float2(n0r, n0i);
        b = make_float2(n1r, n1i);
    };

    // CROSS: pairs (2m+1, 2m+2) = (b[m], a[m+1]); endpoints scaled by CE
    auto cross = [&](int buf) {
        if (lane == 0)  sm_a[buf][w] = a;
        if (lane == 31) sm_b[buf][w] = b;
        __syncthreads();
        float pbx = __shfl_up_sync(0xffffffffu, b.x, 1);
        float pby = __shfl_up_sync(0xffffffffu, b.y, 1);
        float nax = __shfl_down_sync(0xffffffffu, a.x, 1);
        float nay = __shfl_down_sync(0xffffffffu, a.y, 1);
        if (lane == 0 && w > 0) { float2 v = sm_b[buf][w - 1]; pbx = v.x; pby = v.y; }
        if (lane == 31 && w < 3) { float2 v = sm_a[buf][w + 1]; nax = v.x; nay = v.y; }
        float2 na, nb;
        if (tid > 0) {          // a pairs with prev thread's b
            na = make_float2(fmaf(PX, a.x, -QX * pby), fmaf(PX, a.y, QX * pbx));
        } else {                // global row 0 endpoint
            na = make_float2(CE * a.x, CE * a.y);
        }
        if (tid < N_ - 1) {     // b pairs with next thread's a
            nb = make_float2(fmaf(PX, b.x, -QX * nay), fmaf(PX, b.y, QX * nax));
        } else {                // global row 2N-1 endpoint
            nb = make_float2(CE * b.x, CE * b.y);
        }
        a = na; b = nb;
    };

    // mainloop: layers 0..247 in 31 groups of 8.
    // layer k = 8*kk + j; cross when j even, crossIdx = 4*kk + j/2,
    // buffer parity = (j/2)&1 (compile-time).
    const float2* pre = cs + RING * N_;
    for (int kk = 0; kk < 31; ++kk) {
        #pragma unroll
        for (int j = 0; j < RING; ++j) {
            float2 f = q[j];
            q[j] = pre[j * N_];          // prefetch layer k+8 into freed slot
            layer(f);
            if ((j & 1) == 0) cross((j >> 1) & 1);
        }
        pre += RING * N_;
    }
    // epilogue: layers 248..253 live in slots 0..5
    layer(q[0]); cross(0);   // k=248, crossIdx=124 (even -> buf 0)
    layer(q[1]);             // k=249
    layer(q[2]); cross(1);   // k=250, crossIdx=125
    layer(q[3]);             // k=251
    layer(q[4]); cross(0);   // k=252, crossIdx=126
    layer(q[5]);             // k=253

    // Phase(254): phase only (slot 6)
    {
        float2 f = q[6];
        float ar = fmaf(a.x, f.x, -a.y * f.y);
        float ai = fmaf(a.x, f.y,  a.y * f.x);
        a = make_float2(ar, ai);
    }

    // MMI_OUT + output phase; float32 output = real part, row-major [m][col]
    float orr = fmaf(PM, a.x, -QM * b.y);
    float oii = fmaf(PM, a.y,  QM * b.x);
    float so, co;
    sincosf(theta_out[tid], &so, &co);
    out[tid * N_ + col] = fmaf(orr, co, -oii * so);
}

extern "C" void kernel_launch(void* const* d_in, const int* in_sizes, int n_in,
                              void* d_out, int out_size) {
    // theta_even is the (2N-1)*N array; theta_in first N-sized, theta_out second.
    const float* theta_even = nullptr;
    const float* smalls[2] = {nullptr, nullptr};
    int ns = 0;
    for (int i = 0; i < n_in; ++i) {
        if (in_sizes[i] == NLAYERS * N_) {
            theta_even = (const float*)d_in[i];
        } else if (ns < 2) {
            smalls[ns++] = (const float*)d_in[i];
        }
    }
    const float* theta_in  = smalls[0];
    const float* theta_out = smalls[1];

    precompute_cs_kernel<<<(NLAYERS + RING + 1), N_>>>(theta_even);
    mesh_kernel<<<N_, N_>>>(theta_in, theta_out, (float*)d_out);
}

// round 9
// speedup vs baseline: 1.0008x; 1.0008x over previous
#include <cuda_runtime.h>

// Photonic mesh simulator, N=128. R9: 2 warps per column, 2 pairs per thread.
// R7 (1 warp) was issue-bound (~93% of one SMSP); R8 (4 warps) was sync-bound
// (issue 12.6%, ~200+ cyc/cross in STS-drain + 4-warp BAR skew). This splits
// the difference: per-warp issue halves vs R7; sync is ONE 2-warp barrier per
// cross with a single smem float2 each way.
// Thread t owns pairs 2t,2t+1 (rows 4t..4t+3). Cross boundaries: pair-internal
// (registers), thread-boundary (shfl), warp-boundary 63<->64 (smem, 2 slots).
// Copy-free 8-deep phase ring: layer k consumes slot k&3? no — k&7, reloads
// with k+8; load->use distance = 8 layers >> L2 latency.

#define N_ 128
#define NLAYERS 255   // 2N-1
#define RING 8

// (cos,sin) per (layer, mode); + RING+1 padded layers so prefetch never OOBs
__device__ __align__(16) float2 g_cs[(NLAYERS + RING + 1) * N_];

__global__ void precompute_cs_kernel(const float* __restrict__ theta_even) {
    int idx = blockIdx.x * blockDim.x + threadIdx.x;
    if (idx < NLAYERS * N_) {
        float s, c;
        sincosf(theta_even[idx], &s, &c);
        g_cs[idx] = make_float2(c, s);
    } else if (idx < (NLAYERS + RING + 1) * N_) {
        g_cs[idx] = make_float2(1.0f, 0.0f);  // padding (never used in math)
    }
}

__global__ void __launch_bounds__(64, 1) mesh_kernel(
    const float* __restrict__ theta_in,
    const float* __restrict__ theta_out,
    float* __restrict__ out)
{
    // B_mmi = aM*[[p, iq],[iq, p]], aM=sqrt(0.95), p=sqrt(0.505), q=sqrt(0.495)
    constexpr float PM = 0.6926399f;
    constexpr float QM = 0.6857478f;
    // B_x = aX*[[s, it],[it, s]], aX=sqrt(0.98), s=sqrt(0.01), t=sqrt(0.99)
    constexpr float PX = 0.09899495f;
    constexpr float QX = 0.9849873f;
    constexpr float CE = 0.9849873f;   // endpoint scalar aX*sqrt(1-CT)

    const int t    = threadIdx.x;      // 0..63; owns pairs 2t (p0) and 2t+1 (p1)
    const int lane = t & 31;
    const int w    = t >> 5;           // warp id 0..1
    const int col  = blockIdx.x;       // column

    // warp-boundary patch (pair 63 <-> pair 64), double buffered
    __shared__ float2 sm_a[2];   // a of pair 64 (t=32)
    __shared__ float2 sm_b[2];   // b of pair 63 (t=31)

    // state: pair p0 = rows (4t, 4t+1) -> (a0,b0); pair p1 = rows (4t+2, 4t+3) -> (a1,b1)
    float2 a0 = make_float2(0.f, 0.f), b0 = make_float2(0.f, 0.f);
    float2 a1 = make_float2(0.f, 0.f), b1 = make_float2(0.f, 0.f);
    if ((col >> 1) == t) {
        float si, ci;
        sincosf(theta_in[col], &si, &ci);
        if ((col & 1) == 0) {
            a0 = make_float2(PM * ci, PM * si);
            b0 = make_float2(-QM * si, QM * ci);
        } else {
            a1 = make_float2(PM * ci, PM * si);
            b1 = make_float2(-QM * si, QM * ci);
        }
    }

    // phase ring: thread t needs modes 2t,2t+1 => exactly one float4 per layer
    const float4* cs4 = reinterpret_cast<const float4*>(g_cs) + t;   // 64 float4 per layer
    float4 q[RING];
    #pragma unroll
    for (int j = 0; j < RING; ++j) q[j] = cs4[j * 64];

    // phase (even rows) + MMI_EVEN on both owned pairs
    auto layer = [&](float4 f) {
        {   // pair p0: (c,s) = (f.x, f.y)
            float ar = fmaf(a0.x, f.x, -a0.y * f.y);
            float ai = fmaf(a0.x, f.y,  a0.y * f.x);
            float n0r = fmaf(PM, ar,   -QM * b0.y);
            float n0i = fmaf(PM, ai,    QM * b0.x);
            float n1r = fmaf(PM, b0.x, -QM * ai);
            float n1i = fmaf(PM, b0.y,  QM * ar);
            a0 = make_float2(n0r, n0i);
            b0 = make_float2(n1r, n1i);
        }
        {   // pair p1: (c,s) = (f.z, f.w)
            float ar = fmaf(a1.x, f.z, -a1.y * f.w);
            float ai = fmaf(a1.x, f.w,  a1.y * f.z);
            float n0r = fmaf(PM, ar,   -QM * b1.y);
            float n0i = fmaf(PM, ai,    QM * b1.x);
            float n1r = fmaf(PM, b1.x, -QM * ai);
            float n1i = fmaf(PM, b1.y,  QM * ar);
            a1 = make_float2(n0r, n0i);
            b1 = make_float2(n1r, n1i);
        }
    };

    // CROSS: pairs (2m+1, 2m+2) = (b[m], a[m+1]); endpoints scaled by CE
    auto cross = [&](int buf) {
        if (t == 32) sm_a[buf] = a0;      // warp1 lane0: a of pair 64
        if (t == 31) sm_b[buf] = b1;      // warp0 lane31: b of pair 63
        __syncthreads();
        // neighbors within warp
        float pbx = __shfl_up_sync(0xffffffffu, b1.x, 1);    // prev thread's b1
        float pby = __shfl_up_sync(0xffffffffu, b1.y, 1);
        float nax = __shfl_down_sync(0xffffffffu, a0.x, 1);  // next thread's a0
        float nay = __shfl_down_sync(0xffffffffu, a0.y, 1);
        if (lane == 0 && w == 1) { float2 v = sm_b[buf]; pbx = v.x; pby = v.y; }
        if (lane == 31 && w == 0) { float2 v = sm_a[buf]; nax = v.x; nay = v.y; }

        // internal boundary: (b0, a1)
        float2 nb0 = make_float2(fmaf(PX, b0.x, -QX * a1.y), fmaf(PX, b0.y, QX * a1.x));
        float2 na1 = make_float2(fmaf(PX, a1.x, -QX * b0.y), fmaf(PX, a1.y, QX * b0.x));
        // left boundary: (prev b1, a0)
        float2 na0;
        if (t > 0) {
            na0 = make_float2(fmaf(PX, a0.x, -QX * pby), fmaf(PX, a0.y, QX * pbx));
        } else {            // global row 0 endpoint
            na0 = make_float2(CE * a0.x, CE * a0.y);
        }
        // right boundary: (b1, next a0)
        float2 nb1;
        if (t < 63) {
            nb1 = make_float2(fmaf(PX, b1.x, -QX * nay), fmaf(PX, b1.y, QX * nax));
        } else {            // global row 2N-1 endpoint
            nb1 = make_float2(CE * b1.x, CE * b1.y);
        }
        a0 = na0; b0 = nb0; a1 = na1; b1 = nb1;
    };

    // mainloop: layers 0..247 in 31 groups of 8.
    // layer k = 8*kk + j; cross when j even; crossIdx = 4*kk + j/2;
    // buffer parity = (j/2)&1 (compile-time since 4*kk is even).
    const float4* pre = cs4 + RING * 64;
    for (int kk = 0; kk < 31; ++kk) {
        #pragma unroll
        for (int j = 0; j < RING; ++j) {
            float4 f = q[j];
            q[j] = pre[j * 64];          // prefetch layer k+8 into freed slot
            layer(f);
            if ((j & 1) == 0) cross((j >> 1) & 1);
        }
        pre += RING * 64;
    }
    // epilogue: layers 248..253 live in slots 0..5
    layer(q[0]); cross(0);   // k=248, crossIdx=124 -> buf 0
    layer(q[1]);             // k=249
    layer(q[2]); cross(1);   // k=250, crossIdx=125 -> buf 1
    layer(q[3]);             // k=251
    layer(q[4]); cross(0);   // k=252, crossIdx=126 -> buf 0
    layer(q[5]);             // k=253

    // Phase(254): phase only (slot 6)
    {
        float4 f = q[6];
        float ar = fmaf(a0.x, f.x, -a0.y * f.y);
        float ai = fmaf(a0.x, f.y,  a0.y * f.x);
        a0 = make_float2(ar, ai);
        float br = fmaf(a1.x, f.z, -a1.y * f.w);
        float bi = fmaf(a1.x, f.w,  a1.y * f.z);
        a1 = make_float2(br, bi);
    }

    // MMI_OUT + output phase; float32 output = real part, row-major [m][col]
    {
        const int m = 2 * t;
        float orr = fmaf(PM, a0.x, -QM * b0.y);
        float oii = fmaf(PM, a0.y,  QM * b0.x);
        float so, co;
        sincosf(theta_out[m], &so, &co);
        out[m * N_ + col] = fmaf(orr, co, -oii * so);
    }
    {
        const int m = 2 * t + 1;
        float orr = fmaf(PM, a1.x, -QM * b1.y);
        float oii = fmaf(PM, a1.y,  QM * b1.x);
        float so, co;
        sincosf(theta_out[m], &so, &co);
        out[m * N_ + col] = fmaf(orr, co, -oii * so);
    }
}

extern "C" void kernel_launch(void* const* d_in, const int* in_sizes, int n_in,
                              void* d_out, int out_size) {
    // theta_even is the (2N-1)*N array; theta_in first N-sized, theta_out second.
    const float* theta_even = nullptr;
    const float* smalls[2] = {nullptr, nullptr};
    int ns = 0;
    for (int i = 0; i < n_in; ++i) {
        if (in_sizes[i] == NLAYERS * N_) {
            theta_even = (const float*)d_in[i];
        } else if (ns < 2) {
            smalls[ns++] = (const float*)d_in[i];
        }
    }
    const float* theta_in  = smalls[0];
    const float* theta_out = smalls[1];

    precompute_cs_kernel<<<(NLAYERS + RING + 1), N_>>>(theta_even);
    mesh_kernel<<<N_, 64>>>(theta_in, theta_out, (float*)d_out);
}